// round 9
// baseline (speedup 1.0000x reference)
#include <cuda_runtime.h>
#include <cuda_bf16.h>

// GPTQLinear: out[16,11008] = x[16,4096] @ W^T + bias, W = (q - z) * s, int4 groups of 128.
// Inputs: x f32[16,4096], qweight i32[11008,2048] (one byte/elem, 2 nibbles),
// scales f32[11008,32], zeros f32[11008,32], bias f32[11008]. Output f32[16,11008].

#define OUTF  11008
#define INF   4096
#define NB    16
#define QI    2048
#define NG    32
#define ROWS_PER_WARP 4
#define WARPS 4
#define THREADS 128
#define ROWS_PER_BLOCK 16
#define NBLOCKS (OUTF / ROWS_PER_BLOCK)          // 688
#define CHUNK_COLS 256
#define CHUNK_F4 1024                            // float4 per x chunk (16KB)
#define NCHUNKS 16
#define TITERS 4
#define TT_TOTAL 64                              // total 64-col granules

// smem: x[2][16KB] | qw ring[4][2KB] | sb[4KB]  = 45056 B (occ 5: 5*45KB <= 228KB)
#define SM_X(buf)   ((buf) << 14)
#define SM_QW(slot) (32768 + ((slot) << 11))
#define SM_SB       40960
#define SM_TOTAL    45056

typedef unsigned long long ull;

__device__ float4 g_xpack[QI * 8];               // xT[4096][16], PRE-SWIZZLED per 8KB chunk
__device__ float2 g_sB[OUTF * NG];               // {s, -z*s}

#define FMA2(acc, a, b) asm("fma.rn.f32x2 %0, %1, %2, %0;" : "+l"(acc) : "l"(a), "l"(b))
#define ADD2(d, a, b)   asm("add.rn.f32x2 %0, %1, %2;" : "=l"(d) : "l"(a), "l"(b))
#define PACKW(d, w) do { unsigned _wu = __float_as_uint(w); \
    asm("mov.b64 %0, {%1, %1};" : "=l"(d) : "r"(_wu)); } while (0)

__device__ __forceinline__ void cp16(unsigned dst, const void* src) {
    asm volatile("cp.async.cg.shared.global [%0], [%1], 16;" :: "r"(dst), "l"(src));
}
#define CP_COMMIT() asm volatile("cp.async.commit_group;")
#define CP_WAIT(n)  asm volatile("cp.async.wait_group %0;" :: "n"(n))

// Fused prep: blocks [0,64) transpose x into PRE-SWIZZLED g_xpack; rest build {s,-z*s}.
__global__ void prep_kernel(const float* __restrict__ x,
                            const float* __restrict__ scales,
                            const float* __restrict__ zeros) {
    if (blockIdx.x < 64) {
        __shared__ float tile[NB][65];
        const int c0 = blockIdx.x * 64;
        const int tid = threadIdx.x;
#pragma unroll
        for (int idx = tid; idx < NB * 64; idx += 256) {
            int r = idx >> 6, col = idx & 63;
            tile[r][col] = x[r * INF + c0 + col];
        }
        __syncthreads();
        float* xo = reinterpret_cast<float*>(g_xpack);
#pragma unroll
        for (int idx = tid; idx < NB * 64; idx += 256) {
            int col = idx >> 4, b = idx & 15;
            int j  = (c0 + col) * 4 + (b >> 2);           // float4 index
            int jl = j & 1023;                            // within 16KB chunk
            int dj = (j & ~1023) | (jl ^ ((jl >> 3) & 7)); // bake chunk-local swizzle
            xo[dj * 4 + (b & 3)] = tile[b][col];
        }
    } else {
        int i = (blockIdx.x - 64) * 256 + threadIdx.x;
        float s = scales[i];
        float z = zeros[i];
        g_sB[i] = make_float2(s, -z * s);
    }
}

__global__ __launch_bounds__(THREADS, 5)
void gptq_main_kernel(const int* __restrict__ qw,
                      const float* __restrict__ bias,
                      float* __restrict__ out) {
    __shared__ __align__(128) char smem_raw[SM_TOTAL];

    const int tid  = threadIdx.x;
    const int lane = tid & 31;
    const int warp = tid >> 5;
    const int rb0  = blockIdx.x * ROWS_PER_BLOCK;
    const int o0   = rb0 + warp * ROWS_PER_WARP;
    const int xr   = lane & 7;

    unsigned sm;
    asm("{ .reg .u64 t; cvta.to.shared.u64 t, %1; cvt.u32.u64 %0, t; }"
        : "=r"(sm) : "l"(smem_raw));

    // qw staging: lane l stages row (l>>3), 16B piece (l&7) of each 64-col granule
    const int* qsrc = qw + (o0 + (lane >> 3)) * QI + ((lane & 7) << 2);
    const unsigned qdst = sm + 32768 + (unsigned)(warp * 512 + (lane >> 3) * 128
                                                  + (lane & 7) * 16);

    const float4* gxp = g_xpack;

    // ---- prologue: group X0 = {x chunk 0 + scale table}, then qw granules 0..3 ----
#pragma unroll
    for (int i = 0; i < 8; ++i) {
        int idx = tid + i * THREADS;
        cp16(sm + SM_X(0) + (unsigned)(idx * 16), gxp + idx);
    }
    {
        const char* gsb = reinterpret_cast<const char*>(g_sB + rb0 * NG);
        cp16(sm + SM_SB + (unsigned)(tid * 32),      gsb + tid * 32);
        cp16(sm + SM_SB + (unsigned)(tid * 32 + 16), gsb + tid * 32 + 16);
    }
    CP_COMMIT();
    gxp += CHUNK_F4;
#pragma unroll
    for (int g = 0; g < 4; ++g) {
        cp16(qdst + (unsigned)(g << 11), qsrc);
        qsrc += 32;
        CP_COMMIT();
    }

    ull acc[ROWS_PER_WARP][8];
#pragma unroll
    for (int r = 0; r < ROWS_PER_WARP; ++r)
#pragma unroll
        for (int k = 0; k < 8; ++k) acc[r][k] = 0ull;

    const float2* s_sb = reinterpret_cast<const float2*>(smem_raw + SM_SB)
                         + (warp * ROWS_PER_WARP) * NG;

    int tt = 0;
    for (int c = 0; c < NCHUNKS; ++c) {
        CP_WAIT(4);                 // x chunk c (and everything older) landed
        __syncthreads();            // everyone done with chunk c-1's buffer

        // stage x chunk c+1 into the buffer just freed
        if (c + 1 < NCHUNKS) {
#pragma unroll
            for (int i = 0; i < 8; ++i) {
                int idx = tid + i * THREADS;
                cp16(sm + SM_X((c + 1) & 1) + (unsigned)(idx * 16), gxp + idx);
            }
        }
        CP_COMMIT();
        gxp += CHUNK_F4;

        const float4* s_x = reinterpret_cast<const float4*>(smem_raw + SM_X(c & 1));

#pragma unroll
        for (int t = 0; t < TITERS; ++t) {
            CP_WAIT(4);             // qw granule tt landed

            const int* s_qw = reinterpret_cast<const int*>(smem_raw + SM_QW(tt & 3))
                              + warp * 128;
            const float4* xbase = s_x + (t * 32 + lane) * 8;
            const int gsel = (c << 1) | (t >> 1);

            int bv[ROWS_PER_WARP];
            float2 sB[ROWS_PER_WARP];
#pragma unroll
            for (int r = 0; r < ROWS_PER_WARP; ++r) {
                bv[r] = s_qw[r * 32 + lane];
                sB[r] = s_sb[r * NG + gsel];
            }

            ull w[ROWS_PER_WARP];
            // even columns (low nibble)
#pragma unroll
            for (int r = 0; r < ROWS_PER_WARP; ++r) {
                float q0 = __int_as_float(0x4B000000 | (bv[r] & 15)) - 8388608.0f;
                PACKW(w[r], fmaf(q0, sB[r].x, sB[r].y));
            }
#pragma unroll
            for (int q = 0; q < 4; ++q) {
                ulonglong2 v = *reinterpret_cast<const ulonglong2*>(xbase + (q ^ xr));
#pragma unroll
                for (int r = 0; r < ROWS_PER_WARP; ++r) {
                    FMA2(acc[r][2 * q],     v.x, w[r]);
                    FMA2(acc[r][2 * q + 1], v.y, w[r]);
                }
            }
            // odd columns (high nibble) — reuse w regs
#pragma unroll
            for (int r = 0; r < ROWS_PER_WARP; ++r) {
                float q1 = __int_as_float(0x4B000000 | ((bv[r] >> 4) & 15)) - 8388608.0f;
                PACKW(w[r], fmaf(q1, sB[r].x, sB[r].y));
            }
#pragma unroll
            for (int q = 0; q < 4; ++q) {
                ulonglong2 v = *reinterpret_cast<const ulonglong2*>(xbase + ((q + 4) ^ xr));
#pragma unroll
                for (int r = 0; r < ROWS_PER_WARP; ++r) {
                    FMA2(acc[r][2 * q],     v.x, w[r]);
                    FMA2(acc[r][2 * q + 1], v.y, w[r]);
                }
            }

            // stage qw granule tt+4 into the slot just consumed (thread-local safety)
            if (tt + 4 < TT_TOTAL) cp16(qdst + (unsigned)((tt & 3) << 11), qsrc);
            qsrc += 32;
            CP_COMMIT();
            ++tt;
        }
    }

    // ---- cross-lane reduction: 64-bit shfl butterfly + packed add ----
#pragma unroll
    for (int r = 0; r < ROWS_PER_WARP; ++r)
#pragma unroll
        for (int k = 0; k < 8; ++k) {
            ull v = acc[r][k];
#pragma unroll
            for (int off = 16; off; off >>= 1) {
                ull u = __shfl_xor_sync(0xffffffffu, v, off);
                ADD2(v, v, u);
            }
            acc[r][k] = v;
        }

    // ---- stage output tile [16 batches][16 cols] in smem, coalesced store ----
    CP_WAIT(0);
    __syncthreads();
    float* so = reinterpret_cast<float*>(smem_raw);
#pragma unroll
    for (int r = 0; r < ROWS_PER_WARP; ++r)
#pragma unroll
        for (int k = 0; k < 8; ++k)
            if (lane == r * 8 + k) {
                int col = warp * ROWS_PER_WARP + r;
                so[(2 * k) * ROWS_PER_BLOCK + col] =
                    __uint_as_float((unsigned)(acc[r][k] & 0xffffffffull));
                so[(2 * k + 1) * ROWS_PER_BLOCK + col] =
                    __uint_as_float((unsigned)(acc[r][k] >> 32));
            }
    __syncthreads();

#pragma unroll
    for (int idx = tid; idx < NB * ROWS_PER_BLOCK; idx += THREADS) {
        int b = idx >> 4, col = idx & 15;
        out[b * OUTF + rb0 + col] = so[idx] + bias[rb0 + col];
    }
}

extern "C" void kernel_launch(void* const* d_in, const int* in_sizes, int n_in,
                              void* d_out, int out_size) {
    const float* x      = (const float*)d_in[0];
    const int*   qw     = (const int*)d_in[1];
    const float* scales = (const float*)d_in[2];
    const float* zeros  = (const float*)d_in[3];
    const float* bias   = (const float*)d_in[4];
    float*       out    = (float*)d_out;

    prep_kernel<<<64 + (OUTF * NG) / 256, 256>>>(x, scales, zeros);
    gptq_main_kernel<<<NBLOCKS, THREADS>>>(qw, bias, out);
}

// round 10
// speedup vs baseline: 1.0023x; 1.0023x over previous
#include <cuda_runtime.h>
#include <cuda_bf16.h>

// GPTQLinear: out[16,11008] = x[16,4096] @ W^T + bias, W = (q - z) * s, int4 groups of 128.
// Inputs: x f32[16,4096], qweight i32[11008,2048] (one byte/elem, 2 nibbles),
// scales f32[11008,32], zeros f32[11008,32], bias f32[11008]. Output f32[16,11008].

#define OUTF  11008
#define INF   4096
#define NB    16
#define QI    2048
#define NG    32
#define ROWS_PER_WARP 4
#define WARPS 4
#define THREADS 128
#define ROWS_PER_BLOCK 16
#define NBLOCKS (OUTF / ROWS_PER_BLOCK)          // 688
#define CHUNK_COLS 256
#define CHUNK_F4 1024                            // float4 per x chunk (16KB)
#define NCHUNKS 16
#define TITERS 4
#define TT_TOTAL 64                              // total 64-col granules

// smem: x[2][16KB] | qw ring[4][2KB] | sb[4KB]  = 45056 B (occ 5: 5*45KB <= 228KB)
#define SM_X(buf)   ((buf) << 14)
#define SM_QW(slot) (32768 + ((slot) << 11))
#define SM_SB       40960
#define SM_TOTAL    45056

typedef unsigned long long ull;

__device__ float4 g_xpack[QI * 8];               // xT[4096][16], PRE-SWIZZLED per 8KB chunk
__device__ float2 g_sB[OUTF * NG];               // {s, -z*s}

#define FMA2(acc, a, b) asm("fma.rn.f32x2 %0, %1, %2, %0;" : "+l"(acc) : "l"(a), "l"(b))
#define ADD2(d, a, b)   asm("add.rn.f32x2 %0, %1, %2;" : "=l"(d) : "l"(a), "l"(b))
#define PACKW(d, w) do { unsigned _wu = __float_as_uint(w); \
    asm("mov.b64 %0, {%1, %1};" : "=l"(d) : "r"(_wu)); } while (0)

__device__ __forceinline__ void cp16(unsigned dst, const void* src) {
    asm volatile("cp.async.cg.shared.global [%0], [%1], 16;" :: "r"(dst), "l"(src));
}
#define CP_COMMIT() asm volatile("cp.async.commit_group;")
#define CP_WAIT(n)  asm volatile("cp.async.wait_group %0;" :: "n"(n))

// Fused prep: blocks [0,64) transpose x into PRE-SWIZZLED g_xpack; rest build {s,-z*s}.
__global__ void prep_kernel(const float* __restrict__ x,
                            const float* __restrict__ scales,
                            const float* __restrict__ zeros) {
    if (blockIdx.x < 64) {
        __shared__ float tile[NB][65];
        const int c0 = blockIdx.x * 64;
        const int tid = threadIdx.x;
#pragma unroll
        for (int idx = tid; idx < NB * 64; idx += 256) {
            int r = idx >> 6, col = idx & 63;
            tile[r][col] = x[r * INF + c0 + col];
        }
        __syncthreads();
        float* xo = reinterpret_cast<float*>(g_xpack);
#pragma unroll
        for (int idx = tid; idx < NB * 64; idx += 256) {
            int col = idx >> 4, b = idx & 15;
            int j  = (c0 + col) * 4 + (b >> 2);           // float4 index
            int jl = j & 1023;                            // within 16KB chunk
            int dj = (j & ~1023) | (jl ^ ((jl >> 3) & 7)); // bake chunk-local swizzle
            xo[dj * 4 + (b & 3)] = tile[b][col];
        }
    } else {
        int i = (blockIdx.x - 64) * 256 + threadIdx.x;
        float s = scales[i];
        float z = zeros[i];
        g_sB[i] = make_float2(s, -z * s);
    }
}

__global__ __launch_bounds__(THREADS, 5)
void gptq_main_kernel(const int* __restrict__ qw,
                      const float* __restrict__ bias,
                      float* __restrict__ out) {
    __shared__ __align__(128) char smem_raw[SM_TOTAL];

    const int tid  = threadIdx.x;
    const int lane = tid & 31;
    const int warp = tid >> 5;
    const int rb0  = blockIdx.x * ROWS_PER_BLOCK;
    const int o0   = rb0 + warp * ROWS_PER_WARP;
    const int xr   = lane & 7;

    unsigned sm;
    asm("{ .reg .u64 t; cvta.to.shared.u64 t, %1; cvt.u32.u64 %0, t; }"
        : "=r"(sm) : "l"(smem_raw));

    // qw staging: lane l stages row (l>>3), 16B piece (l&7) of each 64-col granule
    const int* qsrc = qw + (o0 + (lane >> 3)) * QI + ((lane & 7) << 2);
    const unsigned qdst = sm + 32768 + (unsigned)(warp * 512 + (lane >> 3) * 128
                                                  + (lane & 7) * 16);

    const float4* gxp = g_xpack;

    // ---- prologue: group X0 = {x chunk 0 + scale table}, then qw granules 0..3 ----
#pragma unroll
    for (int i = 0; i < 8; ++i) {
        int idx = tid + i * THREADS;
        cp16(sm + SM_X(0) + (unsigned)(idx * 16), gxp + idx);
    }
    {
        const char* gsb = reinterpret_cast<const char*>(g_sB + rb0 * NG);
        cp16(sm + SM_SB + (unsigned)(tid * 32),      gsb + tid * 32);
        cp16(sm + SM_SB + (unsigned)(tid * 32 + 16), gsb + tid * 32 + 16);
    }
    CP_COMMIT();
    gxp += CHUNK_F4;
#pragma unroll
    for (int g = 0; g < 4; ++g) {
        cp16(qdst + (unsigned)(g << 11), qsrc);
        qsrc += 32;
        CP_COMMIT();
    }

    ull acc[ROWS_PER_WARP][8];
#pragma unroll
    for (int r = 0; r < ROWS_PER_WARP; ++r)
#pragma unroll
        for (int k = 0; k < 8; ++k) acc[r][k] = 0ull;

    const float2* s_sb = reinterpret_cast<const float2*>(smem_raw + SM_SB)
                         + (warp * ROWS_PER_WARP) * NG;

    int tt = 0;
    for (int c = 0; c < NCHUNKS; ++c) {
        CP_WAIT(4);                 // x chunk c (and everything older) landed
        __syncthreads();            // everyone done with chunk c-1's buffer

        // stage x chunk c+1 into the buffer just freed
        if (c + 1 < NCHUNKS) {
#pragma unroll
            for (int i = 0; i < 8; ++i) {
                int idx = tid + i * THREADS;
                cp16(sm + SM_X((c + 1) & 1) + (unsigned)(idx * 16), gxp + idx);
            }
        }
        CP_COMMIT();
        gxp += CHUNK_F4;

        const float4* s_x = reinterpret_cast<const float4*>(smem_raw + SM_X(c & 1));

#pragma unroll
        for (int t = 0; t < TITERS; ++t) {
            CP_WAIT(4);             // qw granule tt landed

            const int* s_qw = reinterpret_cast<const int*>(smem_raw + SM_QW(tt & 3))
                              + warp * 128;
            const float4* xbase = s_x + (t * 32 + lane) * 8;
            const int gsel = (c << 1) | (t >> 1);

            int bv[ROWS_PER_WARP];
            float2 sB[ROWS_PER_WARP];
#pragma unroll
            for (int r = 0; r < ROWS_PER_WARP; ++r) {
                bv[r] = s_qw[r * 32 + lane];
                sB[r] = s_sb[r * NG + gsel];
            }

            ull w[ROWS_PER_WARP];
            // even columns (low nibble)
#pragma unroll
            for (int r = 0; r < ROWS_PER_WARP; ++r) {
                float q0 = __int_as_float(0x4B000000 | (bv[r] & 15)) - 8388608.0f;
                PACKW(w[r], fmaf(q0, sB[r].x, sB[r].y));
            }
#pragma unroll
            for (int q = 0; q < 4; ++q) {
                ulonglong2 v = *reinterpret_cast<const ulonglong2*>(xbase + (q ^ xr));
#pragma unroll
                for (int r = 0; r < ROWS_PER_WARP; ++r) {
                    FMA2(acc[r][2 * q],     v.x, w[r]);
                    FMA2(acc[r][2 * q + 1], v.y, w[r]);
                }
            }
            // odd columns (high nibble) — reuse w regs
#pragma unroll
            for (int r = 0; r < ROWS_PER_WARP; ++r) {
                float q1 = __int_as_float(0x4B000000 | ((bv[r] >> 4) & 15)) - 8388608.0f;
                PACKW(w[r], fmaf(q1, sB[r].x, sB[r].y));
            }
#pragma unroll
            for (int q = 0; q < 4; ++q) {
                ulonglong2 v = *reinterpret_cast<const ulonglong2*>(xbase + ((q + 4) ^ xr));
#pragma unroll
                for (int r = 0; r < ROWS_PER_WARP; ++r) {
                    FMA2(acc[r][2 * q],     v.x, w[r]);
                    FMA2(acc[r][2 * q + 1], v.y, w[r]);
                }
            }

            // stage qw granule tt+4 into the slot just consumed (thread-local safety)
            if (tt + 4 < TT_TOTAL) cp16(qdst + (unsigned)((tt & 3) << 11), qsrc);
            qsrc += 32;
            CP_COMMIT();
            ++tt;
        }
    }

    // ---- cross-lane reduction: 64-bit shfl butterfly + packed add ----
#pragma unroll
    for (int r = 0; r < ROWS_PER_WARP; ++r)
#pragma unroll
        for (int k = 0; k < 8; ++k) {
            ull v = acc[r][k];
#pragma unroll
            for (int off = 16; off; off >>= 1) {
                ull u = __shfl_xor_sync(0xffffffffu, v, off);
                ADD2(v, v, u);
            }
            acc[r][k] = v;
        }

    // ---- stage output tile [16 batches][16 cols] in smem, coalesced store ----
    CP_WAIT(0);
    __syncthreads();
    float* so = reinterpret_cast<float*>(smem_raw);
#pragma unroll
    for (int r = 0; r < ROWS_PER_WARP; ++r)
#pragma unroll
        for (int k = 0; k < 8; ++k)
            if (lane == r * 8 + k) {
                int col = warp * ROWS_PER_WARP + r;
                so[(2 * k) * ROWS_PER_BLOCK + col] =
                    __uint_as_float((unsigned)(acc[r][k] & 0xffffffffull));
                so[(2 * k + 1) * ROWS_PER_BLOCK + col] =
                    __uint_as_float((unsigned)(acc[r][k] >> 32));
            }
    __syncthreads();

#pragma unroll
    for (int idx = tid; idx < NB * ROWS_PER_BLOCK; idx += THREADS) {
        int b = idx >> 4, col = idx & 15;
        out[b * OUTF + rb0 + col] = so[idx] + bias[rb0 + col];
    }
}

extern "C" void kernel_launch(void* const* d_in, const int* in_sizes, int n_in,
                              void* d_out, int out_size) {
    const float* x      = (const float*)d_in[0];
    const int*   qw     = (const int*)d_in[1];
    const float* scales = (const float*)d_in[2];
    const float* zeros  = (const float*)d_in[3];
    const float* bias   = (const float*)d_in[4];
    float*       out    = (float*)d_out;

    prep_kernel<<<64 + (OUTF * NG) / 256, 256>>>(x, scales, zeros);
    gptq_main_kernel<<<NBLOCKS, THREADS>>>(qw, bias, out);
}

// round 13
// speedup vs baseline: 2.1229x; 2.1180x over previous
#include <cuda_runtime.h>
#include <cuda_fp16.h>
#include <cstdint>

// GPTQLinear via warp-level mma.sync (m16n8k16 fp16, fp32 accum), exact-integer weights.
// out[b,o] = sum_g s[o,g]*(P[o,b,g] - z[o,g]*Xs[b,g]) + bias[o]
//   P = sum_{k in g} q[o,k]*fp16(x[b,k])   (exact: q in [0,15] is exact in fp16)
//   Xs[b,g] = sum_{k in g} fp16(x[b,k])

#define OUTF  11008
#define INF   4096
#define NB    16
#define QI    2048          // int32 (one packed byte each) per O-row
#define NG    32
#define THREADS 128
#define KSPLIT 8
#define GRID  (86 * KSPLIT)                 // 86 O-tiles(128 rows) x 8 K-splits

__device__ uint4 g_xfrag[128 * 2 * 32];     // [gt=G*4+t][half][lane]; 128KB
__device__ float g_Xs[NB * NG];             // [b][G]
__device__ float g_part[KSPLIT * NB * OUTF];

// byte (2 nibbles) -> f16x2 {lo nibble, hi nibble}, exact
__device__ __forceinline__ unsigned cvt4(int bv) {
    unsigned h = ((unsigned)(bv | (bv << 12)) & 0x000F000Fu) | 0x64006400u;
    unsigned r;
    asm("sub.f16x2 %0, %1, %2;" : "=r"(r) : "r"(h), "r"(0x64006400u));
    return r;
}

#define MMA(d, a0, a1, a2, a3, b0, b1) \
    asm volatile("mma.sync.aligned.m16n8k16.row.col.f32.f16.f16.f32 " \
        "{%0,%1,%2,%3}, {%4,%5,%6,%7}, {%8,%9}, {%0,%1,%2,%3};" \
        : "+f"((d)[0]), "+f"((d)[1]), "+f"((d)[2]), "+f"((d)[3]) \
        : "r"(a0), "r"(a1), "r"(a2), "r"(a3), "r"(b0), "r"(b1))

// ---------------- prep: B-fragment table + per-group fp16 x sums ----------------
__global__ void prep_kernel(const float* __restrict__ x) {
    if (blockIdx.x < 32) {
        // g_xfrag[e]: e = gt*64 + half*32 + lane. 8 consecutive fp16 of x[b] at col c.
        int e = blockIdx.x * 256 + threadIdx.x;       // 8192 entries
        int lane = e & 31, half = (e >> 5) & 1, gt = e >> 6;
        int G = gt >> 2, t = gt & 3, q = lane & 3;
        int b = (lane >> 2) + 8 * half;
        int c = G * 128 + 32 * q + 8 * t;
        const float* xp = x + b * INF + c;
        float4 v0 = *reinterpret_cast<const float4*>(xp);
        float4 v1 = *reinterpret_cast<const float4*>(xp + 4);
        uint4 o;
        __half2 h;
        h = __floats2half2_rn(v0.x, v0.y); o.x = *reinterpret_cast<unsigned*>(&h);
        h = __floats2half2_rn(v0.z, v0.w); o.y = *reinterpret_cast<unsigned*>(&h);
        h = __floats2half2_rn(v1.x, v1.y); o.z = *reinterpret_cast<unsigned*>(&h);
        h = __floats2half2_rn(v1.z, v1.w); o.w = *reinterpret_cast<unsigned*>(&h);
        g_xfrag[e] = o;
    } else {
        int b = blockIdx.x - 32;                      // 16 blocks
        int g = threadIdx.x >> 3, j = threadIdx.x & 7;
        const float* xp = x + b * INF + g * 128 + j * 16;
        float sum = 0.f;
#pragma unroll
        for (int u = 0; u < 16; ++u)
            sum += __half2float(__float2half_rn(xp[u]));
#pragma unroll
        for (int off = 4; off; off >>= 1)
            sum += __shfl_down_sync(0xffffffffu, sum, off, 8);
        if (j == 0) g_Xs[b * NG + g] = sum;
    }
}

// ---------------- main: register-resident dequant + mma.sync ----------------
__global__ __launch_bounds__(THREADS)
void gptq_mma_kernel(const int* __restrict__ qw,
                     const float* __restrict__ scales,
                     const float* __restrict__ zeros) {
    const int tid = threadIdx.x, lane = tid & 31, warp = tid >> 5;
    const int kq = blockIdx.x & (KSPLIT - 1), ot = blockIdx.x / KSPLIT;
    const int G0 = kq * 4;
    const int o_base = ot * 128 + warp * 32;
    const int q = lane & 3, rowg = lane >> 2;

    // qweight row pointers: r = mt*2 + rowhalf -> row o_base + r*8 + rowg
    const int4* qp[4];
#pragma unroll
    for (int r = 0; r < 4; ++r)
        qp[r] = reinterpret_cast<const int4*>(qw + (o_base + r * 8 + rowg) * QI);

    float acc[16];                    // [mt][half][4]
#pragma unroll
    for (int i = 0; i < 16; ++i) acc[i] = 0.f;

#pragma unroll
    for (int g = 0; g < 4; ++g) {
        const int G = G0 + g;
        float P[16];
#pragma unroll
        for (int i = 0; i < 16; ++i) P[i] = 0.f;

#pragma unroll
        for (int t = 0; t < 4; ++t) {
            const uint4* bf = g_xfrag + (G * 4 + t) * 64 + lane;
            uint4 u0 = bf[0];         // batches 0-7, steps 2t,2t+1
            uint4 u1 = bf[32];        // batches 8-15
            const int qi = G * 16 + 4 * q + t;
#pragma unroll
            for (int mt = 0; mt < 2; ++mt) {
                int4 vL = qp[mt * 2][qi];       // row lo: 16 ints? (4 ints, steps 2t,2t+1)
                int4 vH = qp[mt * 2 + 1][qi];   // row hi (+8)
                unsigned aL0 = cvt4(vL.x), aH0 = cvt4(vH.x);
                unsigned aL1 = cvt4(vL.y), aH1 = cvt4(vH.y);
                MMA(P + mt * 8,     aL0, aH0, aL1, aH1, u0.x, u0.y);
                MMA(P + mt * 8 + 4, aL0, aH0, aL1, aH1, u1.x, u1.y);
                unsigned bL0 = cvt4(vL.z), bH0 = cvt4(vH.z);
                unsigned bL1 = cvt4(vL.w), bH1 = cvt4(vH.w);
                MMA(P + mt * 8,     bL0, bH0, bL1, bH1, u0.z, u0.w);
                MMA(P + mt * 8 + 4, bL0, bH0, bL1, bH1, u1.z, u1.w);
            }
        }

        // epilogue: per-group rescale in fp32
#pragma unroll
        for (int mt = 0; mt < 2; ++mt) {
            int oL = o_base + mt * 16 + rowg, oH = oL + 8;
            float sL = scales[oL * NG + G], zL = zeros[oL * NG + G];
            float sH = scales[oH * NG + G], zH = zeros[oH * NG + G];
#pragma unroll
            for (int h = 0; h < 2; ++h) {
                int bb = 2 * q + 8 * h;
                float X0 = g_Xs[bb * NG + G], X1 = g_Xs[(bb + 1) * NG + G];
                float* Pp = P + mt * 8 + h * 4;
                float* ap = acc + mt * 8 + h * 4;
                ap[0] += sL * fmaf(-zL, X0, Pp[0]);
                ap[1] += sL * fmaf(-zL, X1, Pp[1]);
                ap[2] += sH * fmaf(-zH, X0, Pp[2]);
                ap[3] += sH * fmaf(-zH, X1, Pp[3]);
            }
        }
    }

    // store K-split partials
    float* dst = g_part + kq * (NB * OUTF);
#pragma unroll
    for (int mt = 0; mt < 2; ++mt) {
        int oL = o_base + mt * 16 + rowg, oH = oL + 8;
#pragma unroll
        for (int h = 0; h < 2; ++h) {
            int bb = 2 * q + 8 * h;
            float* ap = acc + mt * 8 + h * 4;
            dst[bb * OUTF + oL]       = ap[0];
            dst[(bb + 1) * OUTF + oL] = ap[1];
            dst[bb * OUTF + oH]       = ap[2];
            dst[(bb + 1) * OUTF + oH] = ap[3];
        }
    }
}

// ---------------- reduce: sum K-split partials + bias ----------------
__global__ void reduce_kernel(const float* __restrict__ bias, float* __restrict__ out) {
    int t = blockIdx.x * 256 + threadIdx.x;       // 688*256 = NB*OUTF exactly
    int oc = t % OUTF;
    float v = bias[oc];
#pragma unroll
    for (int k = 0; k < KSPLIT; ++k) v += g_part[k * (NB * OUTF) + t];
    out[t] = v;
}

extern "C" void kernel_launch(void* const* d_in, const int* in_sizes, int n_in,
                              void* d_out, int out_size) {
    const float* x      = (const float*)d_in[0];
    const int*   qw     = (const int*)d_in[1];
    const float* scales = (const float*)d_in[2];
    const float* zeros  = (const float*)d_in[3];
    const float* bias   = (const float*)d_in[4];
    float*       out    = (float*)d_out;

    prep_kernel<<<48, 256>>>(x);
    gptq_mma_kernel<<<GRID, THREADS>>>(qw, scales, zeros);
    reduce_kernel<<<688, 256>>>(bias, out);
}

// round 14
// speedup vs baseline: 2.8333x; 1.3346x over previous
#include <cuda_runtime.h>
#include <cuda_fp16.h>
#include <cstdint>

// GPTQLinear via warp-level mma.sync (m16n8k16 fp16, fp32 accum), exact-integer weights.
// out[b,o] = sum_g s[o,g]*(P[o,b,g] - z[o,g]*Xs[b,g]) + bias[o]
//   P = sum_{k in g} q[o,k]*fp16(x[b,k])   (exact: q in [0,15] is exact in fp16)
//   Xs[b,g] = sum_{k in g} fp16(x[b,k])

#define OUTF  11008
#define INF   4096
#define NB    16
#define QI    2048          // int32 (one packed byte each) per O-row
#define NG    32
#define THREADS 128
#define KSPLIT 8
#define GRID  (86 * KSPLIT)                 // 86 O-tiles(128 rows) x 8 K-splits

__device__ uint4 g_xfrag[128 * 2 * 32];     // [gt=G*4+t][half][lane]; 128KB
__device__ float g_Xs[NB * NG];             // [b][G]
__device__ float g_part[KSPLIT * NB * OUTF];

// byte (2 nibbles) -> f16x2 {lo nibble, hi nibble}, exact
__device__ __forceinline__ unsigned cvt4(int bv) {
    unsigned h = ((unsigned)(bv | (bv << 12)) & 0x000F000Fu) | 0x64006400u;
    unsigned r;
    asm("sub.f16x2 %0, %1, %2;" : "=r"(r) : "r"(h), "r"(0x64006400u));
    return r;
}

#define MMA(d, a0, a1, a2, a3, b0, b1) \
    asm volatile("mma.sync.aligned.m16n8k16.row.col.f32.f16.f16.f32 " \
        "{%0,%1,%2,%3}, {%4,%5,%6,%7}, {%8,%9}, {%0,%1,%2,%3};" \
        : "+f"((d)[0]), "+f"((d)[1]), "+f"((d)[2]), "+f"((d)[3]) \
        : "r"(a0), "r"(a1), "r"(a2), "r"(a3), "r"(b0), "r"(b1))

// ---------------- prep: B-fragment table + per-group fp16 x sums ----------------
// blocks [0,64): g_xfrag, one entry per thread (8192 entries).
// blocks [64,192): g_Xs, one warp per (b,g) pair (512 warps).
__global__ void prep_kernel(const float* __restrict__ x) {
    if (blockIdx.x < 64) {
        int e = blockIdx.x * 128 + threadIdx.x;       // 8192 entries
        int lane = e & 31, half = (e >> 5) & 1, gt = e >> 6;
        int G = gt >> 2, t = gt & 3, q = lane & 3;
        int b = (lane >> 2) + 8 * half;
        int c = G * 128 + 32 * t + 8 * q;             // k-permuted (matches main)
        const float* xp = x + b * INF + c;
        float4 v0 = *reinterpret_cast<const float4*>(xp);
        float4 v1 = *reinterpret_cast<const float4*>(xp + 4);
        uint4 o;
        __half2 h;
        h = __floats2half2_rn(v0.x, v0.y); o.x = *reinterpret_cast<unsigned*>(&h);
        h = __floats2half2_rn(v0.z, v0.w); o.y = *reinterpret_cast<unsigned*>(&h);
        h = __floats2half2_rn(v1.x, v1.y); o.z = *reinterpret_cast<unsigned*>(&h);
        h = __floats2half2_rn(v1.z, v1.w); o.w = *reinterpret_cast<unsigned*>(&h);
        g_xfrag[e] = o;
    } else {
        int w = (blockIdx.x - 64) * 4 + (threadIdx.x >> 5);   // 512 warps
        int lane = threadIdx.x & 31;
        int b = w >> 5, g = w & 31;
        float4 v = *reinterpret_cast<const float4*>(x + b * INF + g * 128 + lane * 4);
        float sum = __half2float(__float2half_rn(v.x))
                  + __half2float(__float2half_rn(v.y))
                  + __half2float(__float2half_rn(v.z))
                  + __half2float(__float2half_rn(v.w));
#pragma unroll
        for (int off = 16; off; off >>= 1)
            sum += __shfl_xor_sync(0xffffffffu, sum, off);
        if (lane == 0) g_Xs[b * NG + g] = sum;
    }
}

// ---------------- main: register-resident dequant + mma.sync ----------------
__global__ __launch_bounds__(THREADS)
void gptq_mma_kernel(const int* __restrict__ qw,
                     const float* __restrict__ scales,
                     const float* __restrict__ zeros) {
    const int tid = threadIdx.x, lane = tid & 31, warp = tid >> 5;
    const int kq = blockIdx.x & (KSPLIT - 1), ot = blockIdx.x / KSPLIT;
    const int G0 = kq * 4;
    const int o_base = ot * 128 + warp * 32;
    const int q = lane & 3, rowg = lane >> 2;

    // qweight row pointers: r = mt*2 + rowhalf -> row o_base + r*8 + rowg
    const int4* qp[4];
#pragma unroll
    for (int r = 0; r < 4; ++r)
        qp[r] = reinterpret_cast<const int4*>(qw + (o_base + r * 8 + rowg) * QI);

    float acc[16];                    // [mt][half][4]
#pragma unroll
    for (int i = 0; i < 16; ++i) acc[i] = 0.f;

#pragma unroll
    for (int g = 0; g < 4; ++g) {
        const int G = G0 + g;
        float P[16];
#pragma unroll
        for (int i = 0; i < 16; ++i) P[i] = 0.f;

#pragma unroll
        for (int t = 0; t < 4; ++t) {
            const uint4* bf = g_xfrag + (G * 4 + t) * 64 + lane;
            uint4 u0 = bf[0];         // batches 0-7, this k-slice
            uint4 u1 = bf[32];        // batches 8-15
            const int qi = G * 16 + 4 * t + q;    // 64B-contiguous across lanes q=0..3
#pragma unroll
            for (int mt = 0; mt < 2; ++mt) {
                int4 vL = qp[mt * 2][qi];       // row lo
                int4 vH = qp[mt * 2 + 1][qi];   // row hi (+8)
                unsigned aL0 = cvt4(vL.x), aH0 = cvt4(vH.x);
                unsigned aL1 = cvt4(vL.y), aH1 = cvt4(vH.y);
                MMA(P + mt * 8,     aL0, aH0, aL1, aH1, u0.x, u0.y);
                MMA(P + mt * 8 + 4, aL0, aH0, aL1, aH1, u1.x, u1.y);
                unsigned bL0 = cvt4(vL.z), bH0 = cvt4(vH.z);
                unsigned bL1 = cvt4(vL.w), bH1 = cvt4(vH.w);
                MMA(P + mt * 8,     bL0, bH0, bL1, bH1, u0.z, u0.w);
                MMA(P + mt * 8 + 4, bL0, bH0, bL1, bH1, u1.z, u1.w);
            }
        }

        // epilogue: per-group rescale in fp32
#pragma unroll
        for (int mt = 0; mt < 2; ++mt) {
            int oL = o_base + mt * 16 + rowg, oH = oL + 8;
            float sL = scales[oL * NG + G], zL = zeros[oL * NG + G];
            float sH = scales[oH * NG + G], zH = zeros[oH * NG + G];
#pragma unroll
            for (int h = 0; h < 2; ++h) {
                int bb = 2 * q + 8 * h;
                float X0 = g_Xs[bb * NG + G], X1 = g_Xs[(bb + 1) * NG + G];
                float* Pp = P + mt * 8 + h * 4;
                float* ap = acc + mt * 8 + h * 4;
                ap[0] += sL * fmaf(-zL, X0, Pp[0]);
                ap[1] += sL * fmaf(-zL, X1, Pp[1]);
                ap[2] += sH * fmaf(-zH, X0, Pp[2]);
                ap[3] += sH * fmaf(-zH, X1, Pp[3]);
            }
        }
    }

    // store K-split partials
    float* dst = g_part + kq * (NB * OUTF);
#pragma unroll
    for (int mt = 0; mt < 2; ++mt) {
        int oL = o_base + mt * 16 + rowg, oH = oL + 8;
#pragma unroll
        for (int h = 0; h < 2; ++h) {
            int bb = 2 * q + 8 * h;
            float* ap = acc + mt * 8 + h * 4;
            dst[bb * OUTF + oL]       = ap[0];
            dst[(bb + 1) * OUTF + oL] = ap[1];
            dst[bb * OUTF + oH]       = ap[2];
            dst[(bb + 1) * OUTF + oH] = ap[3];
        }
    }
}

// ---------------- reduce: sum K-split partials + bias (vectorized) ----------------
__global__ void reduce_kernel(const float* __restrict__ bias, float* __restrict__ out) {
    int t4 = (blockIdx.x * 256 + threadIdx.x) * 4;   // 172*256*4 = NB*OUTF exactly
    int oc = t4 % OUTF;                              // OUTF % 4 == 0: no row crossing
    float4 v = *reinterpret_cast<const float4*>(bias + oc);
#pragma unroll
    for (int k = 0; k < KSPLIT; ++k) {
        float4 p = *reinterpret_cast<const float4*>(g_part + k * (NB * OUTF) + t4);
        v.x += p.x; v.y += p.y; v.z += p.z; v.w += p.w;
    }
    *reinterpret_cast<float4*>(out + t4) = v;
}

extern "C" void kernel_launch(void* const* d_in, const int* in_sizes, int n_in,
                              void* d_out, int out_size) {
    const float* x      = (const float*)d_in[0];
    const int*   qw     = (const int*)d_in[1];
    const float* scales = (const float*)d_in[2];
    const float* zeros  = (const float*)d_in[3];
    const float* bias   = (const float*)d_in[4];
    float*       out    = (float*)d_out;

    prep_kernel<<<192, 128>>>(x);
    gptq_mma_kernel<<<GRID, THREADS>>>(qw, scales, zeros);
    reduce_kernel<<<172, 256>>>(bias, out);
}